// round 5
// baseline (speedup 1.0000x reference)
#include <cuda_runtime.h>

// Problem constants
#define Bn   32
#define Cn   128
#define Tn   8192
#define Kn   5
#define MCn  256          // M*C
#define PADn 2

// conv tiling
#define OT   64           // output-channel tile
#define TT   128          // time tile
#define ICC  16           // input-channel chunk

// Scratch (no cudaMalloc allowed)
__device__ float g_gap[Bn * Cn];
__device__ float g_h[Bn * MCn];

// ---------------------------------------------------------------------------
// Stage 1: masked global average pool.  gap[b,c] = sum_t x[b,c,t] / len[b]
// One block per (b,c) row; float4 strided reads; memory-bound.
// ---------------------------------------------------------------------------
__global__ void gap_kernel(const float* __restrict__ x, const int* __restrict__ lens) {
    int bc = blockIdx.x;  // b*Cn + c
    const float4* row = reinterpret_cast<const float4*>(x + (size_t)bc * Tn);
    float s = 0.f;
    for (int i = threadIdx.x; i < Tn / 4; i += blockDim.x) {
        float4 v = row[i];
        s += (v.x + v.y) + (v.z + v.w);
    }
    for (int o = 16; o; o >>= 1) s += __shfl_down_sync(0xffffffffu, s, o);
    __shared__ float sm[8];
    int w = threadIdx.x >> 5, l = threadIdx.x & 31;
    if (l == 0) sm[w] = s;
    __syncthreads();
    if (threadIdx.x == 0) {
        float tot = 0.f;
        #pragma unroll
        for (int i = 0; i < 8; i++) tot += sm[i];
        g_gap[bc] = tot / (float)lens[bc / Cn];
    }
}

// ---------------------------------------------------------------------------
// Stage 2: h[b,j] = sigmoid(gap[b,:] . w1[j,:] + b1[j]).  32 blocks x 256 thr.
// ---------------------------------------------------------------------------
__global__ void fc1_kernel(const float* __restrict__ w1, const float* __restrict__ b1) {
    int b = blockIdx.x;
    __shared__ float sg[Cn];
    if (threadIdx.x < Cn) sg[threadIdx.x] = g_gap[b * Cn + threadIdx.x];
    __syncthreads();
    int j = threadIdx.x;  // 256 threads == MCn
    const float* wr = w1 + (size_t)j * Cn;
    float z = b1[j];
    #pragma unroll 8
    for (int c = 0; c < Cn; c++) z += sg[c] * wr[c];
    g_h[b * MCn + j] = 1.f / (1.f + expf(-z));
}

// ---------------------------------------------------------------------------
// Stage 3: dynamic per-sample conv.
// out[b,o,t] = sum_{i,k} (w2[o*640+i*5+k] * h[b, 2o + (i>=64)]) * x[b,i,t+k-2]
// Block tile: 64 o x 128 t, one b. Thread tile: 4 o x 8 t, packed as f32x2
// pairs (4 accum pairs per o). Weights premultiplied by h and stored as
// duplicated float2 in shared -> LDS.64 gives ready-packed operand.
// ---------------------------------------------------------------------------
__global__ __launch_bounds__(256, 2)
void conv_kernel(const float* __restrict__ x, const float* __restrict__ w2,
                 float* __restrict__ out) {
    const int t0 = blockIdx.x * TT;
    const int o0 = blockIdx.y * OT;
    const int b  = blockIdx.z;

    __shared__ float2 sW[OT * ICC * Kn];             // [o][i][k], value duplicated
    __shared__ __align__(16) float sX[ICC][TT + 4];  // halo of K-1 = 4
    __shared__ float sH[2 * OT];

    const int tx = threadIdx.x;   // 16 -> time
    const int ty = threadIdx.y;   // 16 -> out-channel
    const int tid = ty * 16 + tx;

    if (tid < 2 * OT) sH[tid] = g_h[b * MCn + 2 * o0 + tid];

    unsigned long long acc[4][4];
    #pragma unroll
    for (int oo = 0; oo < 4; oo++)
        #pragma unroll
        for (int p = 0; p < 4; p++) acc[oo][p] = 0ull;

    for (int ic0 = 0; ic0 < Cn; ic0 += ICC) {
        __syncthreads();  // previous compute done (and sH visible on 1st iter)

        // fill weight tile: e = o*(ICC*Kn) + i*Kn + k  (linear in both read+write)
        for (int e = tid; e < OT * ICC * Kn; e += 256) {
            int o = e / (ICC * Kn);
            int r = e - o * (ICC * Kn);
            int i = r / Kn;
            float wv = w2[(size_t)(o0 + o) * (Cn * Kn) + ic0 * Kn + r];
            float v  = wv * sH[2 * o + ((ic0 + i) >= 64 ? 1 : 0)];
            sW[e] = make_float2(v, v);
        }
        // fill x tile with halo
        for (int e = tid; e < ICC * (TT + 4); e += 256) {
            int i = e / (TT + 4);
            int c = e - i * (TT + 4);
            int t = t0 - PADn + c;
            sX[i][c] = (t >= 0 && t < Tn)
                       ? x[((size_t)(b * Cn + ic0 + i)) * Tn + t] : 0.f;
        }
        __syncthreads();

        const unsigned long long* sWu =
            reinterpret_cast<const unsigned long long*>(sW);

        #pragma unroll 4
        for (int i = 0; i < ICC; i++) {
            const float4* xr = reinterpret_cast<const float4*>(&sX[i][tx * 8]);
            float4 a0 = xr[0], a1 = xr[1], a2 = xr[2];
            float xv[12] = {a0.x, a0.y, a0.z, a0.w,
                            a1.x, a1.y, a1.z, a1.w,
                            a2.x, a2.y, a2.z, a2.w};
            unsigned long long xp[11];
            #pragma unroll
            for (int j = 0; j < 11; j++)
                asm("mov.b64 %0, {%1, %2};" : "=l"(xp[j]) : "f"(xv[j]), "f"(xv[j + 1]));

            #pragma unroll
            for (int oo = 0; oo < 4; oo++) {
                const unsigned long long* wr =
                    sWu + ((size_t)(ty * 4 + oo) * ICC + i) * Kn;
                #pragma unroll
                for (int k = 0; k < Kn; k++) {
                    unsigned long long ww = wr[k];
                    #pragma unroll
                    for (int p = 0; p < 4; p++)
                        asm("fma.rn.f32x2 %0, %1, %2, %0;"
                            : "+l"(acc[oo][p]) : "l"(ww), "l"(xp[2 * p + k]));
                }
            }
        }
    }

    // store 4 o x 8 t per thread as float2
    const int obase = b * Cn + o0 + ty * 4;
    #pragma unroll
    for (int oo = 0; oo < 4; oo++) {
        float* orow = out + (size_t)(obase + oo) * Tn + t0 + tx * 8;
        #pragma unroll
        for (int p = 0; p < 4; p++) {
            float lo, hi;
            asm("mov.b64 {%0, %1}, %2;" : "=f"(lo), "=f"(hi) : "l"(acc[oo][p]));
            reinterpret_cast<float2*>(orow)[p] = make_float2(lo, hi);
        }
    }
}

// ---------------------------------------------------------------------------
extern "C" void kernel_launch(void* const* d_in, const int* in_sizes, int n_in,
                              void* d_out, int out_size) {
    const float* x    = (const float*)d_in[0];
    const int*   lens = (const int*)  d_in[1];
    const float* w1   = (const float*)d_in[2];
    const float* b1   = (const float*)d_in[3];
    const float* w2   = (const float*)d_in[4];
    float* out = (float*)d_out;

    gap_kernel<<<Bn * Cn, 256>>>(x, lens);
    fc1_kernel<<<Bn, 256>>>(w1, b1);
    conv_kernel<<<dim3(Tn / TT, Cn / OT, Bn), dim3(16, 16)>>>(x, w2, out);
}